// round 2
// baseline (speedup 1.0000x reference)
#include <cuda_runtime.h>
#include <cuda_bf16.h>
#include <math.h>

// Problem constants
#define Bb 2
#define Nn 4096
#define Mm 32
#define Cc 256
#define Hh 8
#define CHh 32
#define T2 625
#define SCALE 0.17677669529663687f   // 32^-0.5
#define ROWS (Bb*Nn)                  // 8192

// Scratch (static device allocations are allowed)
__device__ float g_qkv[(size_t)ROWS * 768];      // per row: [q(256) | kv(512) interleaved h*(k32,v32)]
__device__ float g_attnout[(size_t)ROWS * Cc];   // attention output before proj
__device__ float g_pe[T2 * Hh];                  // pe_table = pre_table @ W_pe + b_pe
__device__ int   g_mask_is_u8;                   // 1 if cluster_mask stored as bytes, 0 if int32

// ---------------------------------------------------------------------------
// mask dtype detection: read buffer as uint32; packed-uint8 bools produce
// values > 1 with probability ~1 over 2048 words.
// ---------------------------------------------------------------------------
__global__ void detect_mask_kernel(const unsigned int* __restrict__ m)
{
    if (threadIdx.x != 0 || blockIdx.x != 0) return;
    int u8 = 0;
    for (int i = 0; i < 2048; i++) {
        if (m[i] > 1u) { u8 = 1; break; }
    }
    g_mask_is_u8 = u8;
}

// ---------------------------------------------------------------------------
// pe_table kernel: (625,5)@(5,8)+b  -> g_pe[t*8+h]
// ---------------------------------------------------------------------------
__global__ void pe_kernel(const float* __restrict__ pre_table,
                          const float* __restrict__ W_pe,
                          const float* __restrict__ b_pe)
{
    int i = blockIdx.x * blockDim.x + threadIdx.x;
    if (i >= T2 * Hh) return;
    int t = i >> 3;
    int h = i & 7;
    float acc = b_pe[h];
#pragma unroll
    for (int j = 0; j < 5; j++)
        acc += pre_table[t * 5 + j] * W_pe[j * Hh + h];
    g_pe[i] = acc;
}

// ---------------------------------------------------------------------------
// Generic tiled SGEMM: Cout[m, colofs + n] = A[m,:] @ W[:,n] + bias[n]
// A: (Mrows x K) row-major, W: (K x Ncols) row-major, Cout leading dim ldout.
// BM=BN=128, BK=8, 256 threads, 8x8 microtile.
// ---------------------------------------------------------------------------
__global__ __launch_bounds__(256) void sgemm_kernel(
    const float* __restrict__ A, const float* __restrict__ W,
    const float* __restrict__ bias, float* __restrict__ Cout,
    int Mrows, int K, int Ncols, int ldout, int colofs)
{
    __shared__ float As[8][128];
    __shared__ float Bs[8][128];

    const int tid = threadIdx.x;
    const int block_m = blockIdx.y * 128;
    const int block_n = blockIdx.x * 128;

    const int arow = tid >> 1;          // 0..127
    const int acol = (tid & 1) * 4;     // 0 or 4
    const int brow = tid >> 5;          // 0..7
    const int bcol = (tid & 31) * 4;    // 0..124

    const float* Aptr = A + (size_t)(block_m + arow) * K + acol;
    const float* Wptr = W + (size_t)brow * Ncols + block_n + bcol;

    float acc[8][8];
#pragma unroll
    for (int i = 0; i < 8; i++)
#pragma unroll
        for (int j = 0; j < 8; j++) acc[i][j] = 0.f;

    const int tr = (tid >> 4) * 8;      // 0..120
    const int tc = (tid & 15) * 8;      // 0..120

    for (int k0 = 0; k0 < K; k0 += 8) {
        float4 av = *(const float4*)(Aptr + k0);
        As[acol + 0][arow] = av.x;
        As[acol + 1][arow] = av.y;
        As[acol + 2][arow] = av.z;
        As[acol + 3][arow] = av.w;
        float4 bv = *(const float4*)(Wptr + (size_t)k0 * Ncols);
        *(float4*)&Bs[brow][bcol] = bv;
        __syncthreads();

#pragma unroll
        for (int k = 0; k < 8; k++) {
            float af[8], bf[8];
#pragma unroll
            for (int i = 0; i < 8; i++) af[i] = As[k][tr + i];
#pragma unroll
            for (int j = 0; j < 8; j++) bf[j] = Bs[k][tc + j];
#pragma unroll
            for (int i = 0; i < 8; i++)
#pragma unroll
                for (int j = 0; j < 8; j++)
                    acc[i][j] = fmaf(af[i], bf[j], acc[i][j]);
        }
        __syncthreads();
    }

    float bvals[8];
#pragma unroll
    for (int j = 0; j < 8; j++) bvals[j] = bias[block_n + tc + j];
#pragma unroll
    for (int i = 0; i < 8; i++) {
        float* crow = Cout + (size_t)(block_m + tr + i) * ldout + colofs + block_n + tc;
#pragma unroll
        for (int j = 0; j < 8; j++) crow[j] = acc[i][j] + bvals[j];
    }
}

// ---------------------------------------------------------------------------
// Fused gather + scores + softmax + weighted-V kernel.
// One block per (b,n) row, 256 threads = 8 warps, warp h = head h.
// Lane m handles member m.
// ---------------------------------------------------------------------------
__global__ __launch_bounds__(256) void attn_kernel(
    const int* __restrict__ member_idx,
    const void* __restrict__ cluster_mask,
    const int* __restrict__ pe_idx,
    const float* __restrict__ blank_k,
    const float* __restrict__ blank_v)
{
    __shared__ float q_sh[256];
    __shared__ float vsc[8 * 32 * 33];   // attn-scaled V rows, padded stride 33

    const int bn   = blockIdx.x;         // b*N + n
    const int tid  = threadIdx.x;
    const int h    = tid >> 5;
    const int lane = tid & 31;

    const size_t rowbase = (size_t)bn * 768;
    q_sh[tid] = g_qkv[rowbase + tid];
    __syncthreads();

    const int mbase = bn * Mm;
    const int idx = member_idx[mbase + lane];
    const int pid = pe_idx[mbase + lane];
    bool msk;
    if (g_mask_is_u8)
        msk = ((const unsigned char*)cluster_mask)[mbase + lane] != 0;
    else
        msk = ((const int*)cluster_mask)[mbase + lane] != 0;

    const int b = bn >> 12;              // N = 4096
    const size_t krow = ((size_t)(b * Nn + idx)) * 768 + 256 + h * 64;

    const float* qh = q_sh + h * 32;

    // score = q . k_gathered
    const float4* kp = (const float4*)(g_qkv + krow);
    float score = 0.f;
#pragma unroll
    for (int i = 0; i < 8; i++) {
        float4 kk = kp[i];
        score = fmaf(kk.x, qh[4*i+0], score);
        score = fmaf(kk.y, qh[4*i+1], score);
        score = fmaf(kk.z, qh[4*i+2], score);
        score = fmaf(kk.w, qh[4*i+3], score);
    }
    score = score * SCALE + g_pe[pid * Hh + h];
    if (!msk) score = -3.0e38f;

    // blank score (uniform across lanes; computed redundantly)
    float bs = 0.f;
#pragma unroll
    for (int c = 0; c < 32; c++)
        bs = fmaf(qh[c], blank_k[h * 32 + c], bs);
    bs *= SCALE;

    // softmax over 33 entries (32 member scores + blank)
    float mx = score;
#pragma unroll
    for (int o = 16; o > 0; o >>= 1)
        mx = fmaxf(mx, __shfl_xor_sync(0xFFFFFFFFu, mx, o));
    mx = fmaxf(mx, bs);

    float p  = __expf(score - mx);
    float pb = __expf(bs - mx);
    float s = p;
#pragma unroll
    for (int o = 16; o > 0; o >>= 1)
        s += __shfl_xor_sync(0xFFFFFFFFu, s, o);
    s += pb;
    const float inv = 1.f / s;
    const float a  = p * inv;
    const float ab = pb * inv;

    // gather V row, scale by attn weight, stage in padded shared
    const float4* vp = (const float4*)(g_qkv + krow + 32);
    float* vs = vsc + (h * 32 + lane) * 33;
#pragma unroll
    for (int i = 0; i < 8; i++) {
        float4 vv = vp[i];
        vs[4*i+0] = a * vv.x;
        vs[4*i+1] = a * vv.y;
        vs[4*i+2] = a * vv.z;
        vs[4*i+3] = a * vv.w;
    }
    __syncwarp();

    // lane c sums column c over all 32 members + blank term
    float out = ab * blank_v[h * 32 + lane];
    const float* vcol = vsc + h * 32 * 33 + lane;
#pragma unroll
    for (int m = 0; m < 32; m++)
        out += vcol[m * 33];

    g_attnout[(size_t)bn * Cc + h * 32 + lane] = out;
}

// ---------------------------------------------------------------------------
// launch
// ---------------------------------------------------------------------------
extern "C" void kernel_launch(void* const* d_in, const int* in_sizes, int n_in,
                              void* d_out, int out_size)
{
    // Fixed leading inputs
    const float* feat   = (const float*)d_in[0];
    const int*   member = (const int*)d_in[1];
    const void*  mask   = d_in[2];
    const int*   peidx  = (const int*)d_in[3];

    // Locate pre_table by its unique element count (625*5 = 3125); handles
    // presence/absence of the scalar global_attn input.
    int p = 4;
    for (int i = 4; i < n_in; i++) {
        if (in_sizes[i] == 3125) { p = i; break; }
    }
    const float* pre_table = (const float*)d_in[p];
    const float* Wq        = (const float*)d_in[p + 1];
    const float* bq        = (const float*)d_in[p + 2];
    const float* Wkv       = (const float*)d_in[p + 3];
    const float* bkv       = (const float*)d_in[p + 4];
    const float* W_pe      = (const float*)d_in[p + 5];
    const float* b_pe      = (const float*)d_in[p + 6];
    const float* blank_k   = (const float*)d_in[p + 7];
    const float* blank_v   = (const float*)d_in[p + 8];
    const float* Wproj     = (const float*)d_in[p + 9];
    const float* bproj     = (const float*)d_in[p + 10];
    float* out = (float*)d_out;

    float* qkv = nullptr;
    float* attnout = nullptr;
    cudaGetSymbolAddress((void**)&qkv, g_qkv);
    cudaGetSymbolAddress((void**)&attnout, g_attnout);

    // mask dtype detection + pe table
    detect_mask_kernel<<<1, 32>>>((const unsigned int*)mask);
    pe_kernel<<<(T2 * Hh + 255) / 256, 256>>>(pre_table, W_pe, b_pe);

    // Q projection -> qkv cols [0,256)
    {
        dim3 grid(Cc / 128, ROWS / 128);
        sgemm_kernel<<<grid, 256>>>(feat, Wq, bq, qkv, ROWS, Cc, Cc, 768, 0);
    }
    // KV projection -> qkv cols [256,768)
    {
        dim3 grid(512 / 128, ROWS / 128);
        sgemm_kernel<<<grid, 256>>>(feat, Wkv, bkv, qkv, ROWS, Cc, 512, 768, 256);
    }

    // fused attention
    attn_kernel<<<ROWS, 256>>>(member, mask, peidx, blank_k, blank_v);

    // output projection -> d_out
    {
        dim3 grid(Cc / 128, ROWS / 128);
        sgemm_kernel<<<grid, 256>>>(attnout, Wproj, bproj, out, ROWS, Cc, Cc, Cc, 0);
    }
}

// round 3
// speedup vs baseline: 1.2160x; 1.2160x over previous
#include <cuda_runtime.h>
#include <cuda_bf16.h>
#include <math.h>

// Problem constants
#define Bb 2
#define Nn 4096
#define Mm 32
#define Cc 256
#define Hh 8
#define CHh 32
#define T2 625
#define SCALE 0.17677669529663687f   // 32^-0.5
#define ROWS (Bb*Nn)                  // 8192
#define SW 513                        // smem kv row stride (odd -> conflict-free)
#define ATTN_SMEM ((32*SW + 256) * 4) // 66688 bytes

// Scratch
__device__ float g_qkv[(size_t)ROWS * 768];      // per row: [q(256) | per-head (k32,v32) x8]
__device__ float g_attnout[(size_t)ROWS * Cc];
__device__ float g_pe[T2 * Hh];
__device__ int   g_mask_is_u8;

// ---------------------------------------------------------------------------
__global__ void detect_mask_kernel(const unsigned int* __restrict__ m)
{
    if (threadIdx.x != 0 || blockIdx.x != 0) return;
    int u8 = 0;
    for (int i = 0; i < 2048; i++) {
        if (m[i] > 1u) { u8 = 1; break; }
    }
    g_mask_is_u8 = u8;
}

// ---------------------------------------------------------------------------
__global__ void pe_kernel(const float* __restrict__ pre_table,
                          const float* __restrict__ W_pe,
                          const float* __restrict__ b_pe)
{
    int i = blockIdx.x * blockDim.x + threadIdx.x;
    if (i >= T2 * Hh) return;
    int t = i >> 3;
    int h = i & 7;
    float acc = b_pe[h];
#pragma unroll
    for (int j = 0; j < 5; j++)
        acc += pre_table[t * 5 + j] * W_pe[j * Hh + h];
    g_pe[i] = acc;
}

// ---------------------------------------------------------------------------
// Tiled SGEMM: Cout[m, colofs+n] = A[m,:] @ W[:,n] + bias[n]
// BM=BN=128, BK=16, 256 threads, 8x8 microtile.
// ---------------------------------------------------------------------------
__global__ __launch_bounds__(256) void sgemm_kernel(
    const float* __restrict__ A, const float* __restrict__ W,
    const float* __restrict__ bias, float* __restrict__ Cout,
    int Mrows, int K, int Ncols, int ldout, int colofs)
{
    __shared__ float As[16][128];
    __shared__ float Bs[16][128];

    const int tid = threadIdx.x;
    const int block_m = blockIdx.y * 128;
    const int block_n = blockIdx.x * 128;

    const int arow = tid >> 1;          // 0..127
    const int acol = (tid & 1) * 8;     // 0 or 8
    const int brow = tid >> 4;          // 0..15
    const int bcol = (tid & 15) * 8;    // 0..120

    const float* Aptr = A + (size_t)(block_m + arow) * K + acol;

    float acc[8][8];
#pragma unroll
    for (int i = 0; i < 8; i++)
#pragma unroll
        for (int j = 0; j < 8; j++) acc[i][j] = 0.f;

    const int tr = (tid >> 4) * 8;      // 0..120
    const int tc = (tid & 15) * 8;      // 0..120

    for (int k0 = 0; k0 < K; k0 += 16) {
        float4 a0 = *(const float4*)(Aptr + k0);
        float4 a1 = *(const float4*)(Aptr + k0 + 4);
        As[acol + 0][arow] = a0.x;
        As[acol + 1][arow] = a0.y;
        As[acol + 2][arow] = a0.z;
        As[acol + 3][arow] = a0.w;
        As[acol + 4][arow] = a1.x;
        As[acol + 5][arow] = a1.y;
        As[acol + 6][arow] = a1.z;
        As[acol + 7][arow] = a1.w;
        const float* wrow = W + (size_t)(k0 + brow) * Ncols + block_n;
        float4 b0 = *(const float4*)(wrow + bcol);
        float4 b1 = *(const float4*)(wrow + bcol + 4);
        *(float4*)&Bs[brow][bcol]     = b0;
        *(float4*)&Bs[brow][bcol + 4] = b1;
        __syncthreads();

#pragma unroll
        for (int k = 0; k < 16; k++) {
            float af[8], bf[8];
#pragma unroll
            for (int i = 0; i < 8; i++) af[i] = As[k][tr + i];
#pragma unroll
            for (int j = 0; j < 8; j++) bf[j] = Bs[k][tc + j];
#pragma unroll
            for (int i = 0; i < 8; i++)
#pragma unroll
                for (int j = 0; j < 8; j++)
                    acc[i][j] = fmaf(af[i], bf[j], acc[i][j]);
        }
        __syncthreads();
    }

    float bvals[8];
#pragma unroll
    for (int j = 0; j < 8; j++) bvals[j] = bias[block_n + tc + j];
#pragma unroll
    for (int i = 0; i < 8; i++) {
        float* crow = Cout + (size_t)(block_m + tr + i) * ldout + colofs + block_n + tc;
#pragma unroll
        for (int j = 0; j < 8; j++) crow[j] = acc[i][j] + bvals[j];
    }
}

// ---------------------------------------------------------------------------
// Fused gather + scores + softmax + weighted-V, coalesced smem staging.
// One block per (b,n). 256 threads = 8 warps (warp = head).
// Phase 1: cooperatively stage all 32 member KV rows (512 floats each,
//          contiguous in g_qkv) into smem with row stride SW=513.
// Phase 2: warp h, lane m: score; softmax in-warp.
// Phase 3: warp h, lane c: out[c] = sum_m a[m]*v[m][c] + ab*blank_v.
// ---------------------------------------------------------------------------
__global__ __launch_bounds__(256) void attn_kernel(
    const int* __restrict__ member_idx,
    const void* __restrict__ cluster_mask,
    const int* __restrict__ pe_idx,
    const float* __restrict__ blank_k,
    const float* __restrict__ blank_v)
{
    extern __shared__ float smem[];
    float* kv  = smem;            // 32 rows x SW
    float* qsh = smem + 32 * SW;  // 256

    const int bn   = blockIdx.x;
    const int tid  = threadIdx.x;
    const int h    = tid >> 5;
    const int lane = tid & 31;
    const int b    = bn >> 12;     // N = 4096

    // ---- phase 1: stage q + gathered kv ----
    qsh[tid] = g_qkv[(size_t)bn * 768 + tid];

    const int mbase = bn * Mm;
    const int mrow = tid >> 3;     // 0..31  (member handled by this thread-octet)
    const int sub  = tid & 7;      // 0..7
    const int gidx = __ldg(member_idx + mbase + mrow);
    const float4* src = (const float4*)(g_qkv + ((size_t)(b * Nn + gidx)) * 768 + 256);
    float* dst = kv + mrow * SW;
#pragma unroll
    for (int j = 0; j < 16; j++) {
        int p4 = j * 8 + sub;      // float4 index within the 512-float row
        float4 v = src[p4];
        int w = p4 * 4;
        dst[w + 0] = v.x;
        dst[w + 1] = v.y;
        dst[w + 2] = v.z;
        dst[w + 3] = v.w;
    }
    __syncthreads();

    // ---- phase 2: score + softmax (lane = member m) ----
    const float* qh = qsh + h * 32;
    const float* krow = kv + lane * SW + h * 64;
    float score = 0.f;
#pragma unroll
    for (int c = 0; c < 32; c++)
        score = fmaf(qh[c], krow[c], score);

    const int pid = pe_idx[mbase + lane];
    bool msk;
    if (g_mask_is_u8)
        msk = ((const unsigned char*)cluster_mask)[mbase + lane] != 0;
    else
        msk = ((const int*)cluster_mask)[mbase + lane] != 0;
    score = score * SCALE + g_pe[pid * Hh + h];
    if (!msk) score = -3.0e38f;

    // blank score via warp product+reduce (uniform result)
    float bsp = qh[lane] * blank_k[h * 32 + lane];
#pragma unroll
    for (int o = 16; o > 0; o >>= 1)
        bsp += __shfl_xor_sync(0xFFFFFFFFu, bsp, o);
    const float bs = bsp * SCALE;

    float mx = score;
#pragma unroll
    for (int o = 16; o > 0; o >>= 1)
        mx = fmaxf(mx, __shfl_xor_sync(0xFFFFFFFFu, mx, o));
    mx = fmaxf(mx, bs);

    float p  = __expf(score - mx);
    float pb = __expf(bs - mx);
    float s = p;
#pragma unroll
    for (int o = 16; o > 0; o >>= 1)
        s += __shfl_xor_sync(0xFFFFFFFFu, s, o);
    s += pb;
    const float inv = 1.f / s;
    const float a  = p * inv;    // lane m's weight
    const float ab = pb * inv;   // blank weight (uniform)

    // ---- phase 3: weighted V sum (lane = channel c) ----
    float out = ab * blank_v[h * 32 + lane];
    const float* vbase = kv + h * 64 + 32 + lane;
#pragma unroll
    for (int m = 0; m < 32; m++) {
        float w = __shfl_sync(0xFFFFFFFFu, a, m);
        out = fmaf(w, vbase[m * SW], out);
    }

    g_attnout[(size_t)bn * Cc + h * 32 + lane] = out;
}

// ---------------------------------------------------------------------------
extern "C" void kernel_launch(void* const* d_in, const int* in_sizes, int n_in,
                              void* d_out, int out_size)
{
    const float* feat   = (const float*)d_in[0];
    const int*   member = (const int*)d_in[1];
    const void*  mask   = d_in[2];
    const int*   peidx  = (const int*)d_in[3];

    int p = 4;
    for (int i = 4; i < n_in; i++) {
        if (in_sizes[i] == 3125) { p = i; break; }
    }
    const float* pre_table = (const float*)d_in[p];
    const float* Wq        = (const float*)d_in[p + 1];
    const float* bq        = (const float*)d_in[p + 2];
    const float* Wkv       = (const float*)d_in[p + 3];
    const float* bkv       = (const float*)d_in[p + 4];
    const float* W_pe      = (const float*)d_in[p + 5];
    const float* b_pe      = (const float*)d_in[p + 6];
    const float* blank_k   = (const float*)d_in[p + 7];
    const float* blank_v   = (const float*)d_in[p + 8];
    const float* Wproj     = (const float*)d_in[p + 9];
    const float* bproj     = (const float*)d_in[p + 10];
    float* out = (float*)d_out;

    float* qkv = nullptr;
    float* attnout = nullptr;
    cudaGetSymbolAddress((void**)&qkv, g_qkv);
    cudaGetSymbolAddress((void**)&attnout, g_attnout);

    cudaFuncSetAttribute(attn_kernel,
                         cudaFuncAttributeMaxDynamicSharedMemorySize, ATTN_SMEM);

    detect_mask_kernel<<<1, 32>>>((const unsigned int*)mask);
    pe_kernel<<<(T2 * Hh + 255) / 256, 256>>>(pre_table, W_pe, b_pe);

    {   // Q projection -> qkv cols [0,256)
        dim3 grid(Cc / 128, ROWS / 128);
        sgemm_kernel<<<grid, 256>>>(feat, Wq, bq, qkv, ROWS, Cc, Cc, 768, 0);
    }
    {   // KV projection -> qkv cols [256,768)
        dim3 grid(512 / 128, ROWS / 128);
        sgemm_kernel<<<grid, 256>>>(feat, Wkv, bkv, qkv, ROWS, Cc, 512, 768, 256);
    }

    attn_kernel<<<ROWS, 256, ATTN_SMEM>>>(member, mask, peidx, blank_k, blank_v);

    {   // output projection -> d_out
        dim3 grid(Cc / 128, ROWS / 128);
        sgemm_kernel<<<grid, 256>>>(attnout, Wproj, bproj, out, ROWS, Cc, Cc, Cc, 0);
    }
}

// round 4
// speedup vs baseline: 1.8586x; 1.5284x over previous
#include <cuda_runtime.h>
#include <cuda_bf16.h>
#include <math.h>
#include <stdint.h>

// Problem constants
#define Bb 2
#define Nn 4096
#define Mm 32
#define Cc 256
#define Hh 8
#define CHh 32
#define T2 625
#define SCALE 0.17677669529663687f   // 32^-0.5
#define ROWS (Bb*Nn)                  // 8192
#define SW 516                        // smem kv row stride in floats (16B-aligned rows, LDS.128-conflict-free)
#define ATTN_SMEM ((32*SW + 256) * 4) // 67072 bytes

// Scratch
__device__ float g_qkv[(size_t)ROWS * 768];      // per row: [q(256) | per-head (k32,v32) x8]
__device__ float g_attnout[(size_t)ROWS * Cc];
__device__ float g_pe[T2 * Hh];
__device__ int   g_mask_is_u8;

// ---------------------------------------------------------------------------
__global__ void detect_mask_kernel(const unsigned int* __restrict__ m)
{
    if (threadIdx.x != 0 || blockIdx.x != 0) return;
    int u8 = 0;
    for (int i = 0; i < 2048; i++) {
        if (m[i] > 1u) { u8 = 1; break; }
    }
    g_mask_is_u8 = u8;
}

// ---------------------------------------------------------------------------
__global__ void pe_kernel(const float* __restrict__ pre_table,
                          const float* __restrict__ W_pe,
                          const float* __restrict__ b_pe)
{
    int i = blockIdx.x * blockDim.x + threadIdx.x;
    if (i >= T2 * Hh) return;
    int t = i >> 3;
    int h = i & 7;
    float acc = b_pe[h];
#pragma unroll
    for (int j = 0; j < 5; j++)
        acc += pre_table[t * 5 + j] * W_pe[j * Hh + h];
    g_pe[i] = acc;
}

// ---------------------------------------------------------------------------
// TF32 tensor-core GEMM: Cout[m, colofs+n] = A[m,:] @ W[:,n] + bias[n]
// BM=BN=128, BK=16. 256 threads = 8 warps; warp (wm=wid&3, wn=wid>>2)
// owns a 32x64 tile = 2 m-frags x 8 n-frags of m16n8k8.
// ---------------------------------------------------------------------------
__device__ __forceinline__ uint32_t f2tf32(float f)
{
    uint32_t r;
    asm("cvt.rna.tf32.f32 %0, %1;" : "=r"(r) : "f"(f));
    return r;
}

__device__ __forceinline__ void mma_tf32(float* d, const uint32_t* a, const uint32_t* b)
{
    asm volatile(
        "mma.sync.aligned.m16n8k8.row.col.f32.tf32.tf32.f32 "
        "{%0,%1,%2,%3}, {%4,%5,%6,%7}, {%8,%9}, {%0,%1,%2,%3};"
        : "+f"(d[0]), "+f"(d[1]), "+f"(d[2]), "+f"(d[3])
        : "r"(a[0]), "r"(a[1]), "r"(a[2]), "r"(a[3]), "r"(b[0]), "r"(b[1]));
}

__global__ __launch_bounds__(256, 2) void tf32_gemm_kernel(
    const float* __restrict__ A, const float* __restrict__ W,
    const float* __restrict__ bias, float* __restrict__ Cout,
    int K, int Ncols, int ldout, int colofs)
{
    __shared__ uint32_t As[128][20];   // [m][k], pitch 20 -> conflict-free frag loads
    __shared__ uint32_t Bs[16][136];   // [k][n], pitch 136 -> conflict-free frag loads

    const int tid = threadIdx.x;
    const int block_m = blockIdx.y * 128;
    const int block_n = blockIdx.x * 128;

    const int wid = tid >> 5;
    const int lane = tid & 31;
    const int wm = (wid & 3) * 32;     // warp m offset in tile
    const int wn = (wid >> 2) * 64;    // warp n offset in tile
    const int lr = lane >> 2;          // 0..7
    const int lc = lane & 3;           // 0..3

    const int arow = tid >> 1;          // 0..127
    const int acol = (tid & 1) * 8;     // 0 or 8
    const int brow = tid >> 4;          // 0..15
    const int bcol = (tid & 15) * 8;    // 0..120

    const float* Aptr = A + (size_t)(block_m + arow) * K + acol;

    float acc[2][8][4];
#pragma unroll
    for (int i = 0; i < 2; i++)
#pragma unroll
        for (int j = 0; j < 8; j++)
#pragma unroll
            for (int t = 0; t < 4; t++) acc[i][j][t] = 0.f;

    for (int k0 = 0; k0 < K; k0 += 16) {
        // stage A (convert to tf32)
        float4 a0 = *(const float4*)(Aptr + k0);
        float4 a1 = *(const float4*)(Aptr + k0 + 4);
        As[arow][acol + 0] = f2tf32(a0.x);
        As[arow][acol + 1] = f2tf32(a0.y);
        As[arow][acol + 2] = f2tf32(a0.z);
        As[arow][acol + 3] = f2tf32(a0.w);
        As[arow][acol + 4] = f2tf32(a1.x);
        As[arow][acol + 5] = f2tf32(a1.y);
        As[arow][acol + 6] = f2tf32(a1.z);
        As[arow][acol + 7] = f2tf32(a1.w);
        // stage B
        const float* wrow = W + (size_t)(k0 + brow) * Ncols + block_n + bcol;
        float4 b0 = *(const float4*)(wrow);
        float4 b1 = *(const float4*)(wrow + 4);
        Bs[brow][bcol + 0] = f2tf32(b0.x);
        Bs[brow][bcol + 1] = f2tf32(b0.y);
        Bs[brow][bcol + 2] = f2tf32(b0.z);
        Bs[brow][bcol + 3] = f2tf32(b0.w);
        Bs[brow][bcol + 4] = f2tf32(b1.x);
        Bs[brow][bcol + 5] = f2tf32(b1.y);
        Bs[brow][bcol + 6] = f2tf32(b1.z);
        Bs[brow][bcol + 7] = f2tf32(b1.w);
        __syncthreads();

#pragma unroll
        for (int kk = 0; kk < 16; kk += 8) {
            uint32_t afr[2][4], bfr[8][2];
#pragma unroll
            for (int mf = 0; mf < 2; mf++) {
                const int r = wm + mf * 16 + lr;
                afr[mf][0] = As[r][kk + lc];
                afr[mf][1] = As[r + 8][kk + lc];
                afr[mf][2] = As[r][kk + lc + 4];
                afr[mf][3] = As[r + 8][kk + lc + 4];
            }
#pragma unroll
            for (int nf = 0; nf < 8; nf++) {
                const int cn = wn + nf * 8 + lr;
                bfr[nf][0] = Bs[kk + lc][cn];
                bfr[nf][1] = Bs[kk + lc + 4][cn];
            }
#pragma unroll
            for (int mf = 0; mf < 2; mf++)
#pragma unroll
                for (int nf = 0; nf < 8; nf++)
                    mma_tf32(acc[mf][nf], afr[mf], bfr[nf]);
        }
        __syncthreads();
    }

    // epilogue
#pragma unroll
    for (int mf = 0; mf < 2; mf++) {
        const int row0 = block_m + wm + mf * 16 + lr;
#pragma unroll
        for (int nf = 0; nf < 8; nf++) {
            const int col = block_n + wn + nf * 8 + lc * 2;
            float2 bv = *(const float2*)(bias + col);
            float2 v0 = make_float2(acc[mf][nf][0] + bv.x, acc[mf][nf][1] + bv.y);
            float2 v1 = make_float2(acc[mf][nf][2] + bv.x, acc[mf][nf][3] + bv.y);
            *(float2*)(Cout + (size_t)row0 * ldout + colofs + col) = v0;
            *(float2*)(Cout + (size_t)(row0 + 8) * ldout + colofs + col) = v1;
        }
    }
}

// ---------------------------------------------------------------------------
// Fused gather + scores + softmax + weighted-V with cp.async staging.
// ---------------------------------------------------------------------------
__global__ __launch_bounds__(256) void attn_kernel(
    const int* __restrict__ member_idx,
    const void* __restrict__ cluster_mask,
    const int* __restrict__ pe_idx,
    const float* __restrict__ blank_k,
    const float* __restrict__ blank_v)
{
    extern __shared__ float smem[];
    float* kv  = smem;            // 32 rows x SW
    float* qsh = smem + 32 * SW;  // 256

    const int bn   = blockIdx.x;
    const int tid  = threadIdx.x;
    const int h    = tid >> 5;
    const int lane = tid & 31;
    const int b    = bn >> 12;     // N = 4096

    // ---- phase 1: stage q + gathered kv (cp.async) ----
    const int mbase = bn * Mm;
    const int mrow = tid >> 3;     // member handled by this thread-octet
    const int sub  = tid & 7;
    const int gidx = __ldg(member_idx + mbase + mrow);
    const char* src = (const char*)(g_qkv + ((size_t)(b * Nn + gidx)) * 768 + 256);

    uint32_t dst_base;
    {
        float* dp = kv + mrow * SW;
        asm("{ .reg .u64 t; cvta.to.shared.u64 t, %1; cvt.u32.u64 %0, t; }"
            : "=r"(dst_base) : "l"(dp));
    }
#pragma unroll
    for (int j = 0; j < 16; j++) {
        int p4 = j * 8 + sub;      // float4 index within the 512-float row
        asm volatile("cp.async.cg.shared.global [%0], [%1], 16;"
                     :: "r"(dst_base + p4 * 16), "l"(src + p4 * 16));
    }
    asm volatile("cp.async.commit_group;");

    qsh[tid] = g_qkv[(size_t)bn * 768 + tid];

    asm volatile("cp.async.wait_group 0;");
    __syncthreads();

    // ---- phase 2: score + softmax (lane = member m) ----
    const float* qh = qsh + h * 32;
    const float4* krow4 = (const float4*)(kv + lane * SW + h * 64);
    float score = 0.f;
#pragma unroll
    for (int i = 0; i < 8; i++) {
        float4 kk = krow4[i];
        score = fmaf(kk.x, qh[4*i+0], score);
        score = fmaf(kk.y, qh[4*i+1], score);
        score = fmaf(kk.z, qh[4*i+2], score);
        score = fmaf(kk.w, qh[4*i+3], score);
    }

    const int pid = pe_idx[mbase + lane];
    bool msk;
    if (g_mask_is_u8)
        msk = ((const unsigned char*)cluster_mask)[mbase + lane] != 0;
    else
        msk = ((const int*)cluster_mask)[mbase + lane] != 0;
    score = score * SCALE + g_pe[pid * Hh + h];
    if (!msk) score = -3.0e38f;

    // blank score via warp product+reduce (uniform result)
    float bsp = qh[lane] * blank_k[h * 32 + lane];
#pragma unroll
    for (int o = 16; o > 0; o >>= 1)
        bsp += __shfl_xor_sync(0xFFFFFFFFu, bsp, o);
    const float bs = bsp * SCALE;

    float mx = score;
#pragma unroll
    for (int o = 16; o > 0; o >>= 1)
        mx = fmaxf(mx, __shfl_xor_sync(0xFFFFFFFFu, mx, o));
    mx = fmaxf(mx, bs);

    float p  = __expf(score - mx);
    float pb = __expf(bs - mx);
    float s = p;
#pragma unroll
    for (int o = 16; o > 0; o >>= 1)
        s += __shfl_xor_sync(0xFFFFFFFFu, s, o);
    s += pb;
    const float inv = 1.f / s;
    const float a  = p * inv;    // lane m's weight
    const float ab = pb * inv;   // blank weight (uniform)

    // ---- phase 3: weighted V sum (lane = channel c) ----
    float out = ab * blank_v[h * 32 + lane];
    const float* vbase = kv + h * 64 + 32 + lane;
#pragma unroll
    for (int m = 0; m < 32; m++) {
        float w = __shfl_sync(0xFFFFFFFFu, a, m);
        out = fmaf(w, vbase[m * SW], out);
    }

    g_attnout[(size_t)bn * Cc + h * 32 + lane] = out;
}

// ---------------------------------------------------------------------------
extern "C" void kernel_launch(void* const* d_in, const int* in_sizes, int n_in,
                              void* d_out, int out_size)
{
    const float* feat   = (const float*)d_in[0];
    const int*   member = (const int*)d_in[1];
    const void*  mask   = d_in[2];
    const int*   peidx  = (const int*)d_in[3];

    int p = 4;
    for (int i = 4; i < n_in; i++) {
        if (in_sizes[i] == 3125) { p = i; break; }
    }
    const float* pre_table = (const float*)d_in[p];
    const float* Wq        = (const float*)d_in[p + 1];
    const float* bq        = (const float*)d_in[p + 2];
    const float* Wkv       = (const float*)d_in[p + 3];
    const float* bkv       = (const float*)d_in[p + 4];
    const float* W_pe      = (const float*)d_in[p + 5];
    const float* b_pe      = (const float*)d_in[p + 6];
    const float* blank_k   = (const float*)d_in[p + 7];
    const float* blank_v   = (const float*)d_in[p + 8];
    const float* Wproj     = (const float*)d_in[p + 9];
    const float* bproj     = (const float*)d_in[p + 10];
    float* out = (float*)d_out;

    float* qkv = nullptr;
    float* attnout = nullptr;
    cudaGetSymbolAddress((void**)&qkv, g_qkv);
    cudaGetSymbolAddress((void**)&attnout, g_attnout);

    cudaFuncSetAttribute(attn_kernel,
                         cudaFuncAttributeMaxDynamicSharedMemorySize, ATTN_SMEM);

    detect_mask_kernel<<<1, 32>>>((const unsigned int*)mask);
    pe_kernel<<<(T2 * Hh + 255) / 256, 256>>>(pre_table, W_pe, b_pe);

    {   // Q projection -> qkv cols [0,256)
        dim3 grid(Cc / 128, ROWS / 128);
        tf32_gemm_kernel<<<grid, 256>>>(feat, Wq, bq, qkv, Cc, Cc, 768, 0);
    }
    {   // KV projection -> qkv cols [256,768)
        dim3 grid(512 / 128, ROWS / 128);
        tf32_gemm_kernel<<<grid, 256>>>(feat, Wkv, bkv, qkv, Cc, 512, 768, 256);
    }

    attn_kernel<<<ROWS, 256, ATTN_SMEM>>>(member, mask, peidx, blank_k, blank_v);

    {   // output projection -> d_out
        dim3 grid(Cc / 128, ROWS / 128);
        tf32_gemm_kernel<<<grid, 256>>>(attnout, Wproj, bproj, out, Cc, Cc, Cc, 0);
    }
}

// round 5
// speedup vs baseline: 3.2235x; 1.7344x over previous
#include <cuda_runtime.h>
#include <cuda_bf16.h>
#include <math.h>
#include <stdint.h>

// Problem constants
#define Bb 2
#define Nn 4096
#define Mm 32
#define Cc 256
#define Hh 8
#define CHh 32
#define T2 625
#define SCALE 0.17677669529663687f   // 32^-0.5
#define ROWS (Bb*Nn)                  // 8192
#define SW 516                        // smem kv row stride in floats
#define ATTN_SMEM ((32*SW + 256) * 4) // 67072 bytes

// Scratch
__device__ float g_qkv[(size_t)ROWS * 768];      // per row: [q(256) | per-head (k32,v32) x8]
__device__ float g_attnout[(size_t)ROWS * Cc];
__device__ float g_pe[T2 * Hh];
__device__ int   g_mask_is_u8;

// ---------------------------------------------------------------------------
// Parallel mask dtype detection (256 threads, ~1us).
// uint8-packed bools produce uint32 words >1 with overwhelming probability.
// ---------------------------------------------------------------------------
__global__ void detect_mask_kernel(const unsigned int* __restrict__ m)
{
    int found = 0;
#pragma unroll
    for (int j = 0; j < 8; j++) {
        if (m[threadIdx.x + j * 256] > 1u) found = 1;
    }
    int any = __syncthreads_or(found);
    if (threadIdx.x == 0) g_mask_is_u8 = any;
}

// ---------------------------------------------------------------------------
__global__ void pe_kernel(const float* __restrict__ pre_table,
                          const float* __restrict__ W_pe,
                          const float* __restrict__ b_pe)
{
    int i = blockIdx.x * blockDim.x + threadIdx.x;
    if (i >= T2 * Hh) return;
    int t = i >> 3;
    int h = i & 7;
    float acc = b_pe[h];
#pragma unroll
    for (int j = 0; j < 5; j++)
        acc += pre_table[t * 5 + j] * W_pe[j * Hh + h];
    g_pe[i] = acc;
}

// ---------------------------------------------------------------------------
// TF32 tensor-core GEMM with cp.async double buffering.
// Cout[m, colofs+n] = A[m,:] @ W[:,n] + bias[n]
// BM=BN=128, BK=16. 8 warps; warp tile 32x64 (2 x 8 m16n8k8 frags).
// fp32 staged raw via cp.async; cvt to tf32 at fragment-load time.
// ---------------------------------------------------------------------------
__device__ __forceinline__ uint32_t f2tf32(float f)
{
    uint32_t r;
    asm("cvt.rna.tf32.f32 %0, %1;" : "=r"(r) : "f"(f));
    return r;
}

__device__ __forceinline__ void mma_tf32(float* d, const uint32_t* a, const uint32_t* b)
{
    asm volatile(
        "mma.sync.aligned.m16n8k8.row.col.f32.tf32.tf32.f32 "
        "{%0,%1,%2,%3}, {%4,%5,%6,%7}, {%8,%9}, {%0,%1,%2,%3};"
        : "+f"(d[0]), "+f"(d[1]), "+f"(d[2]), "+f"(d[3])
        : "r"(a[0]), "r"(a[1]), "r"(a[2]), "r"(a[3]), "r"(b[0]), "r"(b[1]));
}

__device__ __forceinline__ uint32_t smem_u32(const void* p)
{
    uint32_t r;
    asm("{ .reg .u64 t; cvta.to.shared.u64 t, %1; cvt.u32.u64 %0, t; }"
        : "=r"(r) : "l"(p));
    return r;
}

__global__ __launch_bounds__(256, 2) void tf32_gemm_kernel(
    const float* __restrict__ A, const float* __restrict__ W,
    const float* __restrict__ bias, float* __restrict__ Cout,
    int K, int Ncols, int ldout, int colofs)
{
    __shared__ float As[2][128][20];   // [stage][m][k], pitch 20
    __shared__ float Bs[2][16][136];   // [stage][k][n], pitch 136

    const int tid = threadIdx.x;
    const int block_m = blockIdx.y * 128;
    const int block_n = blockIdx.x * 128;

    const int wid = tid >> 5;
    const int lane = tid & 31;
    const int wm = (wid & 3) * 32;
    const int wn = (wid >> 2) * 64;
    const int lr = lane >> 2;          // 0..7
    const int lc = lane & 3;           // 0..3

    const int arow = tid >> 1;          // 0..127
    const int acol = (tid & 1) * 8;     // 0 or 8
    const int brow = tid >> 4;          // 0..15
    const int bcol = (tid & 15) * 8;    // 0..120

    const float* Aptr = A + (size_t)(block_m + arow) * K + acol;
    const float* Wbase = W + (size_t)brow * Ncols + block_n + bcol;

    float acc[2][8][4];
#pragma unroll
    for (int i = 0; i < 2; i++)
#pragma unroll
        for (int j = 0; j < 8; j++)
#pragma unroll
            for (int t = 0; t < 4; t++) acc[i][j][t] = 0.f;

    const int NIT = K >> 4;

    // async load of one BK=16 tile into stage s
    auto load_tile = [&](int s, int k0) {
        uint32_t ad = smem_u32(&As[s][arow][acol]);
        const char* asrc = (const char*)(Aptr + k0);
        asm volatile("cp.async.ca.shared.global [%0], [%1], 16;" :: "r"(ad), "l"(asrc));
        asm volatile("cp.async.ca.shared.global [%0], [%1], 16;" :: "r"(ad + 16), "l"(asrc + 16));
        uint32_t bd = smem_u32(&Bs[s][brow][bcol]);
        const char* bsrc = (const char*)(Wbase + (size_t)k0 * Ncols);
        asm volatile("cp.async.ca.shared.global [%0], [%1], 16;" :: "r"(bd), "l"(bsrc));
        asm volatile("cp.async.ca.shared.global [%0], [%1], 16;" :: "r"(bd + 16), "l"(bsrc + 16));
    };

    load_tile(0, 0);
    asm volatile("cp.async.commit_group;");

    for (int it = 0; it < NIT; it++) {
        if (it + 1 < NIT) {
            load_tile((it + 1) & 1, (it + 1) << 4);
            asm volatile("cp.async.commit_group;");
            asm volatile("cp.async.wait_group 1;");
        } else {
            asm volatile("cp.async.wait_group 0;");
        }
        __syncthreads();

        const int s = it & 1;
#pragma unroll
        for (int kk = 0; kk < 16; kk += 8) {
            uint32_t afr[2][4], bfr[8][2];
#pragma unroll
            for (int mf = 0; mf < 2; mf++) {
                const int r = wm + mf * 16 + lr;
                afr[mf][0] = f2tf32(As[s][r][kk + lc]);
                afr[mf][1] = f2tf32(As[s][r + 8][kk + lc]);
                afr[mf][2] = f2tf32(As[s][r][kk + lc + 4]);
                afr[mf][3] = f2tf32(As[s][r + 8][kk + lc + 4]);
            }
#pragma unroll
            for (int nf = 0; nf < 8; nf++) {
                const int cn = wn + nf * 8 + lr;
                bfr[nf][0] = f2tf32(Bs[s][kk + lc][cn]);
                bfr[nf][1] = f2tf32(Bs[s][kk + lc + 4][cn]);
            }
#pragma unroll
            for (int mf = 0; mf < 2; mf++)
#pragma unroll
                for (int nf = 0; nf < 8; nf++)
                    mma_tf32(acc[mf][nf], afr[mf], bfr[nf]);
        }
        __syncthreads();
    }

    // epilogue
#pragma unroll
    for (int mf = 0; mf < 2; mf++) {
        const int row0 = block_m + wm + mf * 16 + lr;
#pragma unroll
        for (int nf = 0; nf < 8; nf++) {
            const int col = block_n + wn + nf * 8 + lc * 2;
            float2 bv = *(const float2*)(bias + col);
            float2 v0 = make_float2(acc[mf][nf][0] + bv.x, acc[mf][nf][1] + bv.y);
            float2 v1 = make_float2(acc[mf][nf][2] + bv.x, acc[mf][nf][3] + bv.y);
            *(float2*)(Cout + (size_t)row0 * ldout + colofs + col) = v0;
            *(float2*)(Cout + (size_t)(row0 + 8) * ldout + colofs + col) = v1;
        }
    }
}

// ---------------------------------------------------------------------------
// Fused gather + scores + softmax + weighted-V with cp.async staging.
// ---------------------------------------------------------------------------
__global__ __launch_bounds__(256) void attn_kernel(
    const int* __restrict__ member_idx,
    const void* __restrict__ cluster_mask,
    const int* __restrict__ pe_idx,
    const float* __restrict__ blank_k,
    const float* __restrict__ blank_v)
{
    extern __shared__ float smem[];
    float* kv  = smem;            // 32 rows x SW
    float* qsh = smem + 32 * SW;  // 256

    const int bn   = blockIdx.x;
    const int tid  = threadIdx.x;
    const int h    = tid >> 5;
    const int lane = tid & 31;
    const int b    = bn >> 12;     // N = 4096

    // ---- phase 1: stage q + gathered kv (cp.async) ----
    const int mbase = bn * Mm;
    const int mrow = tid >> 3;
    const int sub  = tid & 7;
    const int gidx = __ldg(member_idx + mbase + mrow);
    const char* src = (const char*)(g_qkv + ((size_t)(b * Nn + gidx)) * 768 + 256);

    uint32_t dst_base = smem_u32(kv + mrow * SW);
#pragma unroll
    for (int j = 0; j < 16; j++) {
        int p4 = j * 8 + sub;
        asm volatile("cp.async.cg.shared.global [%0], [%1], 16;"
                     :: "r"(dst_base + p4 * 16), "l"(src + p4 * 16));
    }
    asm volatile("cp.async.commit_group;");

    qsh[tid] = g_qkv[(size_t)bn * 768 + tid];

    asm volatile("cp.async.wait_group 0;");
    __syncthreads();

    // ---- phase 2: score + softmax (lane = member m) ----
    const float* qh = qsh + h * 32;
    const float4* krow4 = (const float4*)(kv + lane * SW + h * 64);
    float score = 0.f;
#pragma unroll
    for (int i = 0; i < 8; i++) {
        float4 kk = krow4[i];
        score = fmaf(kk.x, qh[4*i+0], score);
        score = fmaf(kk.y, qh[4*i+1], score);
        score = fmaf(kk.z, qh[4*i+2], score);
        score = fmaf(kk.w, qh[4*i+3], score);
    }

    const int pid = pe_idx[mbase + lane];
    bool msk;
    if (g_mask_is_u8)
        msk = ((const unsigned char*)cluster_mask)[mbase + lane] != 0;
    else
        msk = ((const int*)cluster_mask)[mbase + lane] != 0;
    score = score * SCALE + g_pe[pid * Hh + h];
    if (!msk) score = -3.0e38f;

    float bsp = qh[lane] * blank_k[h * 32 + lane];
#pragma unroll
    for (int o = 16; o > 0; o >>= 1)
        bsp += __shfl_xor_sync(0xFFFFFFFFu, bsp, o);
    const float bs = bsp * SCALE;

    float mx = score;
#pragma unroll
    for (int o = 16; o > 0; o >>= 1)
        mx = fmaxf(mx, __shfl_xor_sync(0xFFFFFFFFu, mx, o));
    mx = fmaxf(mx, bs);

    float p  = __expf(score - mx);
    float pb = __expf(bs - mx);
    float s = p;
#pragma unroll
    for (int o = 16; o > 0; o >>= 1)
        s += __shfl_xor_sync(0xFFFFFFFFu, s, o);
    s += pb;
    const float inv = 1.f / s;
    const float a  = p * inv;
    const float ab = pb * inv;

    // ---- phase 3: weighted V sum (lane = channel c) ----
    float out = ab * blank_v[h * 32 + lane];
    const float* vbase = kv + h * 64 + 32 + lane;
#pragma unroll
    for (int m = 0; m < 32; m++) {
        float w = __shfl_sync(0xFFFFFFFFu, a, m);
        out = fmaf(w, vbase[m * SW], out);
    }

    g_attnout[(size_t)bn * Cc + h * 32 + lane] = out;
}

// ---------------------------------------------------------------------------
extern "C" void kernel_launch(void* const* d_in, const int* in_sizes, int n_in,
                              void* d_out, int out_size)
{
    const float* feat   = (const float*)d_in[0];
    const int*   member = (const int*)d_in[1];
    const void*  mask   = d_in[2];
    const int*   peidx  = (const int*)d_in[3];

    int p = 4;
    for (int i = 4; i < n_in; i++) {
        if (in_sizes[i] == 3125) { p = i; break; }
    }
    const float* pre_table = (const float*)d_in[p];
    const float* Wq        = (const float*)d_in[p + 1];
    const float* bq        = (const float*)d_in[p + 2];
    const float* Wkv       = (const float*)d_in[p + 3];
    const float* bkv       = (const float*)d_in[p + 4];
    const float* W_pe      = (const float*)d_in[p + 5];
    const float* b_pe      = (const float*)d_in[p + 6];
    const float* blank_k   = (const float*)d_in[p + 7];
    const float* blank_v   = (const float*)d_in[p + 8];
    const float* Wproj     = (const float*)d_in[p + 9];
    const float* bproj     = (const float*)d_in[p + 10];
    float* out = (float*)d_out;

    float* qkv = nullptr;
    float* attnout = nullptr;
    cudaGetSymbolAddress((void**)&qkv, g_qkv);
    cudaGetSymbolAddress((void**)&attnout, g_attnout);

    cudaFuncSetAttribute(attn_kernel,
                         cudaFuncAttributeMaxDynamicSharedMemorySize, ATTN_SMEM);

    detect_mask_kernel<<<1, 256>>>((const unsigned int*)mask);
    pe_kernel<<<(T2 * Hh + 255) / 256, 256>>>(pre_table, W_pe, b_pe);

    {   // Q projection -> qkv cols [0,256)
        dim3 grid(Cc / 128, ROWS / 128);
        tf32_gemm_kernel<<<grid, 256>>>(feat, Wq, bq, qkv, Cc, Cc, 768, 0);
    }
    {   // KV projection -> qkv cols [256,768)
        dim3 grid(512 / 128, ROWS / 128);
        tf32_gemm_kernel<<<grid, 256>>>(feat, Wkv, bkv, qkv, Cc, 512, 768, 256);
    }

    attn_kernel<<<ROWS, 256, ATTN_SMEM>>>(member, mask, peidx, blank_k, blank_v);

    {   // output projection -> d_out
        dim3 grid(Cc / 128, ROWS / 128);
        tf32_gemm_kernel<<<grid, 256>>>(attnout, Wproj, bproj, out, Cc, Cc, Cc, 0);
    }
}